// round 4
// baseline (speedup 1.0000x reference)
#include <cuda_runtime.h>
#include <math.h>

#define Bv 4
#define Hv 16
#define Nv 8192
#define Dv 64
#define BH (Bv*Hv)
#define SPLIT1 16
#define SPLIT2 16

typedef unsigned long long u64;

// scratch (device globals: no allocation allowed)
__device__ float g_ctx[BH*Dv*Dv];    // [bh][d][e]
__device__ float g_v2sum[BH*Dv];     // [bh][d]
__device__ float g_f[BH*Nv];         // per-token denominator f

__device__ __forceinline__ float elu1(float x) {
    return x > 0.f ? x + 1.f : __expf(x);
}

// pack scalar into both lanes of f32x2
__device__ __forceinline__ u64 pk2(float v) {
    u64 r; asm("mov.b64 %0, {%1,%1};" : "=l"(r) : "f"(v)); return r;
}
// packed fma: d = a*b + c lanewise
__device__ __forceinline__ u64 f2(u64 a, u64 b, u64 c) {
    u64 d; asm("fma.rn.f32x2 %0, %1, %2, %3;" : "=l"(d) : "l"(a), "l"(b), "l"(c));
    return d;
}
__device__ __forceinline__ void upk(u64 v, float& lo, float& hi) {
    asm("mov.b64 {%0,%1}, %2;" : "=f"(lo), "=f"(hi) : "l"(v));
}
// 16B shared load directly into two packed f32x2 regs (no pack movs)
__device__ __forceinline__ void lds2(u64& a, u64& b, const float* p) {
    unsigned r = (unsigned)__cvta_generic_to_shared(p);
    asm volatile("ld.shared.v2.u64 {%0,%1}, [%2];" : "=l"(a), "=l"(b) : "r"(r));
}

__global__ void k0_zero() {
    int i = blockIdx.x*blockDim.x + threadIdx.x;
    if (i < BH*Dv*Dv) g_ctx[i] = 0.f;
    if (i < BH*Dv)    g_v2sum[i] = 0.f;
}

// Pass 1: from K,V compute v2, x, f; accumulate context = v2^T x and sum(v2).
__global__ __launch_bounds__(256) void k1_pass1(
        const float* __restrict__ Kin, const float* __restrict__ Vin,
        const float* __restrict__ mask, const float* __restrict__ curv) {
    const int bh = blockIdx.x;
    const int split = blockIdx.y;
    const float kc = curv[bh & (Hv-1)];
    const int tokens = Nv / SPLIT1;          // 512
    const int n0 = split * tokens;
    __shared__ __align__(16) float ks[32*68];   // K tile -> v2 tile
    __shared__ __align__(16) float vs[32*68];   // V tile -> x tile
    __shared__ float smv[Dv];
    const int tid = threadIdx.x;
    if (tid < Dv) smv[tid] = 0.f;
    const float* Kb = Kin + (size_t)bh*Nv*Dv;
    const float* Vb = Vin + (size_t)bh*Nv*Dv;

    // GEMM layout: two token-halves (tid>>7), within half 16 row-groups x 8 col-groups,
    // each thread owns rows gy*4..+3 (d) and cols gx*8..+7 (e), packed as 4 f32x2 pairs.
    const int gy = (tid & 127) >> 3;
    const int gx = tid & 7;
    const float* ksB = ks + (tid >> 7)*16*68;
    const float* vsB = vs + (tid >> 7)*16*68;

    u64 acc2[4][4];
    #pragma unroll
    for (int i=0;i<4;i++)
        #pragma unroll
        for (int j=0;j<4;j++) acc2[i][j]=0ull;
    float v2loc[8];
    #pragma unroll
    for (int j=0;j<8;j++) v2loc[j]=0.f;

    const int tB = tid >> 3, sub = tid & 7;   // phase-B: 32 tokens x 8 threads

    for (int c0 = 0; c0 < tokens; c0 += 32) {
        const int nb = n0 + c0;
        __syncthreads();
        // Phase A: coalesced load of 32x64 K and V tiles
        #pragma unroll
        for (int r = 0; r < 2; r++) {
            int j = tid + r*256;
            int t = j >> 4, d4 = (j & 15)*4;
            *(float4*)(ks + t*68 + d4) = *(const float4*)(Kb + (size_t)(nb+t)*Dv + d4);
            *(float4*)(vs + t*68 + d4) = *(const float4*)(Vb + (size_t)(nb+t)*Dv + d4);
        }
        __syncthreads();
        // Phase B: per-token scalars, overwrite tiles with v2 / x
        {
            const int n = nb + tB;
            float* vp = vs + tB*68 + sub*8;
            float* kp = ks + tB*68 + sub*8;
            float4 va  = *(float4*)vp;
            float4 vb4 = *(float4*)(vp+4);
            float ss = va.x*va.x + va.y*va.y + va.z*va.z + va.w*va.w
                     + vb4.x*vb4.x + vb4.y*vb4.y + vb4.z*vb4.z + vb4.w*vb4.w;
            ss += __shfl_xor_sync(0xffffffffu, ss, 1);
            ss += __shfl_xor_sync(0xffffffffu, ss, 2);
            ss += __shfl_xor_sync(0xffffffffu, ss, 4);
            float f = fmaxf(1.f + kc*ss, 1e-15f);
            float invf = 1.f / f;
            float gamma = 2.f * invf;
            float gm1 = gamma - 1.f;
            float dn = copysignf(fmaxf(fabsf(gm1), 1e-10f), gm1);  // clamp_abs
            float m = mask[n];
            float dm = dn * m;
            float gd = (gamma / dn) * m;
            float4 ka  = *(float4*)kp;
            float4 kb4 = *(float4*)(kp+4);
            float w0 = dm*elu1(ka.x*invf),  w1 = dm*elu1(ka.y*invf);
            float w2 = dm*elu1(ka.z*invf),  w3 = dm*elu1(ka.w*invf);
            float w4 = dm*elu1(kb4.x*invf), w5 = dm*elu1(kb4.y*invf);
            float w6 = dm*elu1(kb4.z*invf), w7 = dm*elu1(kb4.w*invf);
            *(float4*)kp     = make_float4(w0,w1,w2,w3);
            *(float4*)(kp+4) = make_float4(w4,w5,w6,w7);
            *(float4*)vp     = make_float4(gd*va.x,  gd*va.y,  gd*va.z,  gd*va.w);
            *(float4*)(vp+4) = make_float4(gd*vb4.x, gd*vb4.y, gd*vb4.z, gd*vb4.w);
            v2loc[0]+=w0; v2loc[1]+=w1; v2loc[2]+=w2; v2loc[3]+=w3;
            v2loc[4]+=w4; v2loc[5]+=w5; v2loc[6]+=w6; v2loc[7]+=w7;
            if (sub == 0) g_f[(size_t)bh*Nv + n] = f;
        }
        __syncthreads();
        // GEMM phase: context[d][e] += v2[t][d]*x[t][e], 4x8 per thread, f32x2 packed
        #pragma unroll
        for (int tt = 0; tt < 16; tt++) {
            float4 a = *(const float4*)(ksB + tt*68 + gy*4);
            u64 b0,b1,b2,b3;
            lds2(b0, b1, vsB + tt*68 + gx*8);
            lds2(b2, b3, vsB + tt*68 + gx*8 + 4);
            u64 a0 = pk2(a.x), a1 = pk2(a.y), a2 = pk2(a.z), a3 = pk2(a.w);
            acc2[0][0]=f2(a0,b0,acc2[0][0]); acc2[0][1]=f2(a0,b1,acc2[0][1]);
            acc2[0][2]=f2(a0,b2,acc2[0][2]); acc2[0][3]=f2(a0,b3,acc2[0][3]);
            acc2[1][0]=f2(a1,b0,acc2[1][0]); acc2[1][1]=f2(a1,b1,acc2[1][1]);
            acc2[1][2]=f2(a1,b2,acc2[1][2]); acc2[1][3]=f2(a1,b3,acc2[1][3]);
            acc2[2][0]=f2(a2,b0,acc2[2][0]); acc2[2][1]=f2(a2,b1,acc2[2][1]);
            acc2[2][2]=f2(a2,b2,acc2[2][2]); acc2[2][3]=f2(a2,b3,acc2[2][3]);
            acc2[3][0]=f2(a3,b0,acc2[3][0]); acc2[3][1]=f2(a3,b1,acc2[3][1]);
            acc2[3][2]=f2(a3,b2,acc2[3][2]); acc2[3][3]=f2(a3,b3,acc2[3][3]);
        }
    }
    // epilogue: merge partials (both halves merge via atomics)
    float* ctx = g_ctx + bh*Dv*Dv;
    #pragma unroll
    for (int i=0;i<4;i++) {
        #pragma unroll
        for (int j=0;j<4;j++) {
            float lo, hi; upk(acc2[i][j], lo, hi);
            atomicAdd(&ctx[(gy*4+i)*Dv + gx*8 + 2*j],     lo);
            atomicAdd(&ctx[(gy*4+i)*Dv + gx*8 + 2*j + 1], hi);
        }
    }
    __syncthreads();
    #pragma unroll
    for (int j=0;j<8;j++) atomicAdd(&smv[sub*8+j], v2loc[j]);
    __syncthreads();
    if (tid < Dv) atomicAdd(&g_v2sum[bh*Dv + tid], smv[tid]);
}

// Pass 2: v1, Dn, X = (v1@context)*Dinv, fused radial geometry, write out.
__global__ __launch_bounds__(256) void k2_pass2(
        const float* __restrict__ Qin, const float* __restrict__ curv,
        float* __restrict__ Out) {
    const int bh = blockIdx.x, split = blockIdx.y;
    const float kc = curv[bh & (Hv-1)];
    const float absk = fabsf(kc);
    const float sk = sqrtf(absk + 1e-15f);
    const float maxnorm = (kc < 0.f) ? (1.f - 0.004f)/sqrtf(absk + 1e-15f) : 1e15f;
    __shared__ __align__(16) float ctx_s[Dv*68];
    __shared__ __align__(16) float qv[Dv*68];     // Q tile, then reused as v1^T tile
    __shared__ float v2s[Dv];
    __shared__ float ffs[Dv];
    __shared__ float dinv[Dv];
    const int tid = threadIdx.x;
    for (int i = tid; i < Dv*Dv; i += 256)
        ctx_s[(i>>6)*68 + (i&63)] = g_ctx[bh*Dv*Dv + i];
    if (tid < Dv) v2s[tid] = g_v2sum[bh*Dv + tid];
    const float* Qb = Qin + (size_t)bh*Nv*Dv;
    float* Ob = Out + (size_t)bh*Nv*Dv;
    const int tokens = Nv / SPLIT2;   // 512
    const int n0 = split*tokens;
    const int tB = tid >> 2, sub = tid & 3;   // phase-B: 64 tokens x 4 threads
    const int gy = tid >> 3, gx = tid & 7;    // GEMM: 32 token-groups x 8 col-groups

    for (int c0 = 0; c0 < tokens; c0 += 64) {
        const int nb = n0 + c0;
        __syncthreads();
        // Phase A: coalesced 64x64 Q tile + f scalars
        #pragma unroll
        for (int r = 0; r < 4; r++) {
            int j = tid + r*256;
            int t = j >> 4, d4 = (j & 15)*4;
            *(float4*)(qv + t*68 + d4) = *(const float4*)(Qb + (size_t)(nb+t)*Dv + d4);
        }
        if (tid < Dv) ffs[tid] = g_f[(size_t)bh*Nv + nb + tid];
        __syncthreads();
        // Phase B: v1 into registers + Dn
        float invf = 1.f / ffs[tB];
        float v1r[16];
        float dnp = 0.f;
        #pragma unroll
        for (int r = 0; r < 4; r++) {
            int d0 = sub*16 + r*4;
            float4 q4 = *(float4*)(qv + tB*68 + d0);
            float e0 = elu1(q4.x*invf), e1 = elu1(q4.y*invf);
            float e2 = elu1(q4.z*invf), e3 = elu1(q4.w*invf);
            v1r[r*4+0]=e0; v1r[r*4+1]=e1; v1r[r*4+2]=e2; v1r[r*4+3]=e3;
            dnp += e0*v2s[d0] + e1*v2s[d0+1] + e2*v2s[d0+2] + e3*v2s[d0+3];
        }
        dnp += __shfl_xor_sync(0xffffffffu, dnp, 1);
        dnp += __shfl_xor_sync(0xffffffffu, dnp, 2);
        if (sub == 0) dinv[tB] = 1.f / ((dnp == 0.f) ? 1e-5f : dnp);
        __syncthreads();   // all reads of qv done; now overwrite with v1^T
        #pragma unroll
        for (int r = 0; r < 16; r++) {
            int d = sub*16 + r;
            qv[d*68 + tB] = v1r[r];
        }
        __syncthreads();
        // GEMM: X[t][e] = sum_d v1[t][d]*ctx[d][e], 2 tokens x 8 cols per thread, f32x2
        u64 acc2[2][4];
        #pragma unroll
        for (int i=0;i<2;i++)
            #pragma unroll
            for (int j=0;j<4;j++) acc2[i][j]=0ull;
        #pragma unroll 16
        for (int d = 0; d < Dv; d++) {
            float2 a = *(const float2*)(qv + d*68 + gy*2);
            u64 b0,b1,b2,b3;
            lds2(b0, b1, ctx_s + d*68 + gx*8);
            lds2(b2, b3, ctx_s + d*68 + gx*8 + 4);
            u64 a0 = pk2(a.x), a1 = pk2(a.y);
            acc2[0][0]=f2(a0,b0,acc2[0][0]); acc2[0][1]=f2(a0,b1,acc2[0][1]);
            acc2[0][2]=f2(a0,b2,acc2[0][2]); acc2[0][3]=f2(a0,b3,acc2[0][3]);
            acc2[1][0]=f2(a1,b0,acc2[1][0]); acc2[1][1]=f2(a1,b1,acc2[1][1]);
            acc2[1][2]=f2(a1,b2,acc2[1][2]); acc2[1][3]=f2(a1,b3,acc2[1][3]);
        }
        // epilogue: D_inv scale + radial geometry (project, mobius 0.5, project)
        #pragma unroll
        for (int i = 0; i < 2; i++) {
            int t = gy*2 + i;
            float di = dinv[t];
            float x[8];
            #pragma unroll
            for (int j = 0; j < 4; j++) {
                float lo, hi; upk(acc2[i][j], lo, hi);
                x[2*j] = lo*di; x[2*j+1] = hi*di;
            }
            float ss = 0.f;
            #pragma unroll
            for (int j = 0; j < 8; j++) ss += x[j]*x[j];
            ss += __shfl_xor_sync(0xffffffffu, ss, 1);
            ss += __shfl_xor_sync(0xffffffffu, ss, 2);
            ss += __shfl_xor_sync(0xffffffffu, ss, 4);
            float norm = fmaxf(sqrtf(ss), 1e-15f);
            float s = 1.f, n1 = norm;
            if (norm > maxnorm) { s = maxnorm/norm; n1 = maxnorm; }
            float xn = fmaxf(n1, 1e-15f);
            float tv;
            if (kc < 0.f) {
                // tanh(0.5*artanh(z))/sk == z/((1+sqrt(1-z^2))*sk)
                float z = fminf(sk*xn, 1.f - 1e-7f);
                tv = z / ((1.f + sqrtf(fmaxf(1.f - z*z, 0.f))) * sk);
            } else {
                tv = tanf(0.5f * atanf(sk*xn)) / sk;
            }
            s *= tv / xn;
            float n2 = fabsf(tv);
            if (n2 > maxnorm) s *= maxnorm/n2;
            float* op = Ob + (size_t)(nb+t)*Dv + gx*8;
            *(float4*)op     = make_float4(x[0]*s, x[1]*s, x[2]*s, x[3]*s);
            *(float4*)(op+4) = make_float4(x[4]*s, x[5]*s, x[6]*s, x[7]*s);
        }
    }
}

extern "C" void kernel_launch(void* const* d_in, const int* in_sizes, int n_in,
                              void* d_out, int out_size) {
    const float* Q    = (const float*)d_in[0];
    const float* K    = (const float*)d_in[1];
    const float* V    = (const float*)d_in[2];
    const float* mask = (const float*)d_in[3];
    const float* curv = (const float*)d_in[4];
    float* out = (float*)d_out;
    (void)in_sizes; (void)n_in; (void)out_size;

    k0_zero<<<(BH*Dv*Dv + 255)/256, 256>>>();
    k1_pass1<<<dim3(BH, SPLIT1), 256>>>(K, V, mask, curv);
    k2_pass2<<<dim3(BH, SPLIT2), 256>>>(Q, curv, out);
}